// round 1
// baseline (speedup 1.0000x reference)
#include <cuda_runtime.h>
#include <math.h>

// FBP: 8 views (B=2,C=8,H=128,W=128) -> interp to 128 angles -> ramp filter -> backproject 128x128.
// Restructured: ramp filter as circular conv with h[128], applied to the 8 VIEWS (filter commutes
// with the linear angle interpolation). Per-slice CTA keeps the full 128x128 sinogram in SMEM.

#define BLK 512
#define NSLICE 2048          // B*C*H = 2*8*128
#define SMEM_FLOATS 19200    // see layout below
#define SMEM_BYTES  (SMEM_FLOATS * 4)

__device__ float g_h[128];     // circular ramp-filter kernel
__device__ float g_cosA[128];
__device__ float g_sinA[128];
__device__ float g_wv[128];    // angle-interp fractional weight
__device__ int   g_v0[128];
__device__ int   g_v1[128];

struct Ptrs { const float* p[8]; };

__global__ void fbp_setup() {
    int a = threadIdx.x;           // 0..127
    const float PI = 3.14159265358979323846f;

    // backprojection trig
    float th = (float)a * (PI / 128.0f);
    float sn, cs;
    sincosf(th, &sn, &cs);
    g_cosA[a] = cs;
    g_sinA[a] = sn;

    // view->angle linear interp (half-pixel centers, clamp at edges; matches
    // jax.image.resize weight renormalization since all samples are in range)
    float cv = ((float)a + 0.5f) * (1.0f / 16.0f) - 0.5f;
    cv = fminf(fmaxf(cv, 0.0f), 7.0f);
    int v0 = (int)cv;
    int v1 = v0 + 1; if (v1 > 7) v1 = 7;
    g_v0[a] = v0;
    g_v1[a] = v1;
    g_wv[a] = cv - (float)v0;

    // h[n] = (1/128) * sum_k ramp[k] * cos(2*pi*k*n/128),  ramp[k] = min(k,128-k)/128
    float acc = 0.0f;
    for (int k = 0; k < 128; k++) {
        float ramp = (float)(k < 64 ? k : 128 - k) * (1.0f / 128.0f);
        int ph = (k * a) & 127;                       // exact phase reduction
        acc += ramp * cosf((float)ph * (2.0f * PI / 128.0f));
    }
    g_h[a] = acc * (1.0f / 128.0f);
}

__global__ void __launch_bounds__(BLK) fbp_main(Ptrs P, float* __restrict__ out) {
    extern __shared__ float sm[];
    float* sino  = sm;             // [0, 16384)   : 128 angles x 128 det
    float* fview = sm + 16384;     // [16384,17408): 8 filtered views x 128
    float* raw   = sm + 17408;     // [17408,18432): 8 raw views x 128
    float* sh_h  = sm + 18432;     // 128
    float* shc   = sm + 18560;     // 128 cos
    float* shs   = sm + 18688;     // 128 sin
    float* shwv  = sm + 18816;     // 128
    int*   shv0  = (int*)(sm + 18944); // 128
    int*   shv1  = (int*)(sm + 19072); // 128

    const int tid = threadIdx.x;
    const int s   = blockIdx.x;
    const size_t ibase = (size_t)s * 128;

    if (tid < 128) {
        sh_h[tid] = g_h[tid];
        shc[tid]  = g_cosA[tid];
        shs[tid]  = g_sinA[tid];
        shwv[tid] = g_wv[tid];
        shv0[tid] = g_v0[tid];
        shv1[tid] = g_v1[tid];
    }
    // load the 8 raw view rows for this slice
    for (int idx = tid; idx < 1024; idx += BLK) {
        raw[idx] = P.p[idx >> 7][ibase + (idx & 127)];
    }
    __syncthreads();

    // ramp filter each view: circular conv with h
    for (int idx = tid; idx < 1024; idx += BLK) {
        int v = idx >> 7, wp = idx & 127;
        const float* rv = raw + (v << 7);
        float acc = 0.0f;
        #pragma unroll 4
        for (int w = 0; w < 128; w++)
            acc = fmaf(rv[w], sh_h[(wp - w) & 127], acc);
        fview[idx] = acc;
    }
    __syncthreads();

    // angle interpolation -> full sinogram in SMEM
    for (int idx = tid; idx < 16384; idx += BLK) {
        int a = idx >> 7, w = idx & 127;
        float wv = shwv[a];
        float x0 = fview[(shv0[a] << 7) + w];
        float x1 = fview[(shv1[a] << 7) + w];
        sino[idx] = x0 * (1.0f - wv) + x1 * wv;
    }
    __syncthreads();

    // backprojection: thread -> fixed column j, rows i = i0 + 4*g
    const int j  = tid & 127;
    const int i0 = tid >> 7;                 // 0..3
    const float x = (float)j - 63.5f;
    const float scale = 3.14159265358979323846f / 256.0f;  // pi/(2*128)
    const size_t obase = (size_t)s * 16384;

    #pragma unroll
    for (int ch = 0; ch < 2; ch++) {
        float acc[16];
        #pragma unroll
        for (int k = 0; k < 16; k++) acc[k] = 0.0f;
        const float ybase = (float)(i0 + 64 * ch) - 63.5f;   // i = i0 + 64*ch + 4*k

        for (int a = 0; a < 128; a++) {
            const float cs = shc[a];
            const float sn = shs[a];
            const float tb = fmaf(x, cs, 63.5f);
            const float* srow = sino + (a << 7);
            #pragma unroll
            for (int k = 0; k < 16; k++) {
                float y = ybase + (float)(4 * k);
                float t = fmaf(y, sn, tb);
                t = fminf(fmaxf(t, 0.0f), 127.0f);
                int   ti = (int)t;             // t >= 0, trunc == floor
                float w1 = t - (float)ti;
                int   ti1 = ti + 1; if (ti1 > 127) ti1 = 127;
                float v0 = srow[ti];
                float v1 = srow[ti1];
                acc[k] = fmaf(v0, 1.0f - w1, acc[k]);
                acc[k] = fmaf(v1, w1, acc[k]);
            }
        }
        #pragma unroll
        for (int k = 0; k < 16; k++) {
            int i = i0 + 64 * ch + 4 * k;
            out[obase + (size_t)i * 128 + j] = acc[k] * scale;
        }
    }
}

extern "C" void kernel_launch(void* const* d_in, const int* in_sizes, int n_in,
                              void* d_out, int out_size) {
    (void)in_sizes; (void)n_in; (void)out_size;
    cudaFuncSetAttribute(fbp_main, cudaFuncAttributeMaxDynamicSharedMemorySize, SMEM_BYTES);
    fbp_setup<<<1, 128>>>();
    Ptrs P;
    for (int i = 0; i < 8; i++) P.p[i] = (const float*)d_in[i];
    fbp_main<<<NSLICE, BLK, SMEM_BYTES>>>(P, (float*)d_out);
}

// round 3
// speedup vs baseline: 1.6314x; 1.6314x over previous
#include <cuda_runtime.h>
#include <math.h>

// FBP restructured:
//  - ramp filter as circular conv h[128] applied to the 8 VIEWS (commutes with linear angle interp)
//  - per-CTA: TWO slices' full sinograms resident in SMEM, edge-replicated padding so the
//    backprojection inner loop has NO clamps, and index math is shared across both slices.

#define BLK 512
#define NPAIR 1024            // 2048 slices / 2 per CTA
#define PAD 27
#define ROWSTRIDE 184         // PAD(27) + 128 + 29 round-up, 8-float aligned
#define SLICE_F (128 * ROWSTRIDE)   // 23552 floats per slice sinogram

// SMEM layout (floats):
//   sino : 2 * SLICE_F            = 47104   [0, 47104)
//   fview: 2 * 8 * 128            = 2048    [47104, 49152)
//   raw  : 2 * 8 * 128            = 2048    [49152, 51200)
//   h,cos,sin,wv,v0,v1 : 6 * 128  = 768     [51200, 51968)
#define SMEM_FLOATS 51968
#define SMEM_BYTES  (SMEM_FLOATS * 4)

__device__ float g_h[128];
__device__ float g_cosA[128];
__device__ float g_sinA[128];
__device__ float g_wv[128];
__device__ int   g_v0[128];
__device__ int   g_v1[128];

struct Ptrs { const float* p[8]; };

__global__ void fbp_setup() {
    int a = threadIdx.x;           // 0..127
    const float PI = 3.14159265358979323846f;

    float th = (float)a * (PI / 128.0f);
    float sn, cs;
    sincosf(th, &sn, &cs);
    g_cosA[a] = cs;
    g_sinA[a] = sn;

    // view->angle linear interp (half-pixel, clamped — matches jax.image.resize here)
    float cv = ((float)a + 0.5f) * (1.0f / 16.0f) - 0.5f;
    cv = fminf(fmaxf(cv, 0.0f), 7.0f);
    int v0 = (int)cv;
    int v1 = v0 + 1; if (v1 > 7) v1 = 7;
    g_v0[a] = v0;
    g_v1[a] = v1;
    g_wv[a] = cv - (float)v0;

    // h[n] = (1/128) * sum_k ramp[k] * cos(2*pi*k*n/128), ramp[k] = min(k,128-k)/128
    float acc = 0.0f;
    for (int k = 0; k < 128; k++) {
        float ramp = (float)(k < 64 ? k : 128 - k) * (1.0f / 128.0f);
        int ph = (k * a) & 127;
        acc += ramp * cosf((float)ph * (2.0f * PI / 128.0f));
    }
    g_h[a] = acc * (1.0f / 128.0f);
}

__global__ void __launch_bounds__(BLK) fbp_main(Ptrs P, float* __restrict__ out) {
    extern __shared__ float sm[];
    float* sino  = sm;                 // padded sinograms, 2 slices
    float* fview = sm + 47104;
    float* raw   = sm + 49152;
    float* sh_h  = sm + 51200;
    float* shc   = sm + 51328;
    float* shs   = sm + 51456;
    float* shwv  = sm + 51584;
    int*   shv0  = (int*)(sm + 51712);
    int*   shv1  = (int*)(sm + 51840);

    const int tid = threadIdx.x;
    const int pair = blockIdx.x;
    const size_t in0 = (size_t)(2 * pair) * 128;   // row base for slice0 in inputs

    if (tid < 128) {
        sh_h[tid] = g_h[tid];
        shc[tid]  = g_cosA[tid];
        shs[tid]  = g_sinA[tid];
        shwv[tid] = g_wv[tid];
        shv0[tid] = g_v0[tid];
        shv1[tid] = g_v1[tid];
    }
    // load 2 slices x 8 views x 128
    for (int idx = tid; idx < 2048; idx += BLK) {
        int ss = idx >> 10, rem = idx & 1023;
        raw[idx] = P.p[rem >> 7][in0 + (size_t)ss * 128 + (rem & 127)];
    }
    __syncthreads();

    // ramp-filter each view row (circular conv)
    for (int idx = tid; idx < 2048; idx += BLK) {
        int wp = idx & 127;
        const float* rv = raw + (idx & ~127);
        float acc = 0.0f;
        #pragma unroll 4
        for (int w = 0; w < 128; w++)
            acc = fmaf(rv[w], sh_h[(wp - w) & 127], acc);
        fview[idx] = acc;
    }
    __syncthreads();

    // angle interpolation fused with edge-replicated padding
    for (int idx = tid; idx < 2 * SLICE_F; idx += BLK) {
        int ss  = (idx >= SLICE_F);
        int rem = idx - ss * SLICE_F;
        int a    = rem / ROWSTRIDE;
        int slot = rem - a * ROWSTRIDE;
        int w = slot - PAD;
        w = min(max(w, 0), 127);
        float wv = shwv[a];
        const float* fv = fview + (ss << 10);
        float x0 = fv[(shv0[a] << 7) + w];
        float x1 = fv[(shv1[a] << 7) + w];
        sino[idx] = x0 * (1.0f - wv) + x1 * wv;
    }
    __syncthreads();

    // backprojection: thread -> column j, rows i = i0 + 4k + 64ch; both slices per iter
    const int j  = tid & 127;
    const int i0 = tid >> 7;
    const float x = (float)j - 63.5f;
    const float scale = 3.14159265358979323846f / 256.0f;
    const size_t ob0 = (size_t)(2 * pair) * 16384;

    #pragma unroll
    for (int ch = 0; ch < 2; ch++) {
        float accA[16], accB[16];
        #pragma unroll
        for (int k = 0; k < 16; k++) { accA[k] = 0.0f; accB[k] = 0.0f; }
        const float ybase = (float)(i0 + 64 * ch) - 63.5f;

        for (int a = 0; a < 128; a++) {
            const float cs = shc[a];
            const float sn = shs[a];
            const float tb = fmaf(x, cs, 63.5f + (float)PAD);   // padded center
            const float* r0 = sino + a * ROWSTRIDE;
            #pragma unroll
            for (int k = 0; k < 16; k++) {
                float y = ybase + (float)(4 * k);
                float t = fmaf(y, sn, tb);       // t in (0, 182): trunc == floor, no clamps
                int   ti = (int)t;
                float w1 = t - (float)ti;
                float w0 = 1.0f - w1;
                float a0 = r0[ti];
                float a1 = r0[ti + 1];
                float b0 = r0[ti + SLICE_F];
                float b1 = r0[ti + SLICE_F + 1];
                accA[k] = fmaf(a0, w0, accA[k]);
                accA[k] = fmaf(a1, w1, accA[k]);
                accB[k] = fmaf(b0, w0, accB[k]);
                accB[k] = fmaf(b1, w1, accB[k]);
            }
        }
        #pragma unroll
        for (int k = 0; k < 16; k++) {
            int i = i0 + 64 * ch + 4 * k;
            out[ob0 + (size_t)i * 128 + j]         = accA[k] * scale;
            out[ob0 + 16384 + (size_t)i * 128 + j] = accB[k] * scale;
        }
    }
}

extern "C" void kernel_launch(void* const* d_in, const int* in_sizes, int n_in,
                              void* d_out, int out_size) {
    (void)in_sizes; (void)n_in; (void)out_size;
    cudaFuncSetAttribute(fbp_main, cudaFuncAttributeMaxDynamicSharedMemorySize, SMEM_BYTES);
    fbp_setup<<<1, 128>>>();
    Ptrs P;
    for (int i = 0; i < 8; i++) P.p[i] = (const float*)d_in[i];
    fbp_main<<<NPAIR, BLK, SMEM_BYTES>>>(P, (float*)d_out);
}

// round 5
// speedup vs baseline: 3.2267x; 1.9778x over previous
#include <cuda_runtime.h>
#include <cuda_bf16.h>
#include <math.h>
#include <stdint.h>

// ============================================================================
// FBP as one dense GEMM on the mma.sync (HMMA) path — tcgen05 is unavailable
// because the harness emits compute_103 PTX (no 'a' feature set).
//   out[pixel, slice] = sum_k G[pixel,k] * F[slice,k],  K = 8 views * 128 det
//   bf16 3-product split (Ah*Bh + Ah*Bl + Al*Bh) for fp32-grade accuracy.
// ============================================================================

#define NCHUNK 16                  // K chunks of 64
#define STAGE_B 65536              // Ah/Al/Bh/Bl tiles, 16KB each
#define GEMM_SMEM (2*STAGE_B + 1024)

__device__ float g_h[128];         // ramp filter (circular), scale pi/256 folded
__device__ float g_cosA[128];
__device__ float g_sinA[128];
__device__ float g_wv[128];
__device__ int   g_v0[128];
__device__ int   g_v1[128];

// Pre-swizzled blocked operands:
//  dG*: [128 ptiles][16 kchunks][128 rows x 64 cols bf16, SW128]
//  dF*: [ 16 stiles][16 kchunks][128 rows x 64 cols bf16, SW128]
__device__ __nv_bfloat16 dGh[16384*1024];
__device__ __nv_bfloat16 dGl[16384*1024];
__device__ __nv_bfloat16 dFh[2048*1024];
__device__ __nv_bfloat16 dFl[2048*1024];

struct Ptrs { const float* p[8]; };

__host__ __device__ __forceinline__ uint32_t swz(uint32_t b) {
    return b ^ ((b >> 3) & 0x70);
}

// ---------------------------------------------------------------------------
__global__ void fbp_setup() {
    int a = threadIdx.x;           // 0..127
    const float PI = 3.14159265358979323846f;

    float th = (float)a * (PI / 128.0f);
    float sn, cs;
    sincosf(th, &sn, &cs);
    g_cosA[a] = cs;
    g_sinA[a] = sn;

    float cv = ((float)a + 0.5f) * (1.0f / 16.0f) - 0.5f;
    cv = fminf(fmaxf(cv, 0.0f), 7.0f);
    int v0 = (int)cv;
    int v1 = v0 + 1; if (v1 > 7) v1 = 7;
    g_v0[a] = v0;
    g_v1[a] = v1;
    g_wv[a] = cv - (float)v0;

    float acc = 0.0f;
    for (int k = 0; k < 128; k++) {
        float ramp = (float)(k < 64 ? k : 128 - k) * (1.0f / 128.0f);
        int ph = (k * a) & 127;
        acc += ramp * cosf((float)ph * (2.0f * PI / 128.0f));
    }
    g_h[a] = acc * (1.0f / 128.0f) * (PI / 256.0f);
}

// ---------------------------------------------------------------------------
// F: ramp-filter the 8 views of each slice, bf16 hi/lo split, blocked+swizzled.
__global__ __launch_bounds__(128) void fbp_filter(Ptrs P) {
    __shared__ float raw[8][128];
    __shared__ float hh[128];
    const int t = threadIdx.x;
    const int s = blockIdx.x;              // slice 0..2047
    hh[t] = g_h[t];
    #pragma unroll
    for (int v = 0; v < 8; v++) raw[v][t] = P.p[v][(size_t)s * 128 + t];
    __syncthreads();

    const int r = s & 127, stile = s >> 7;
    #pragma unroll
    for (int v = 0; v < 8; v++) {
        float acc = 0.0f;
        #pragma unroll 4
        for (int w = 0; w < 128; w++)
            acc = fmaf(raw[v][w], hh[(t - w) & 127], acc);
        int kv = v * 128 + t;
        int kc = kv >> 6, c = kv & 63;
        uint32_t idx = (uint32_t)(stile * 16 + kc) * 8192u + (swz(r * 128 + c * 2) >> 1);
        __nv_bfloat16 hi = __float2bfloat16(acc);
        dFh[idx] = hi;
        dFl[idx] = __float2bfloat16(acc - __bfloat162float(hi));
    }
}

// ---------------------------------------------------------------------------
// G: backprojection+interp weights per pixel, bf16 split, blocked+swizzled.
__global__ __launch_bounds__(128) void fbp_gmat() {
    extern __shared__ float g[];           // 32 * 1024 floats
    const int tid = threadIdx.x;
    for (int idx = tid; idx < 32768; idx += 128) g[idx] = 0.0f;
    __syncthreads();

    if (tid < 32) {
        int p = blockIdx.x * 32 + tid;
        float x = (float)(p & 127) - 63.5f;
        float y = (float)(p >> 7)  - 63.5f;
        float* gp = g + tid * 1024;
        for (int a = 0; a < 128; a++) {
            float tt = fmaf(y, g_sinA[a], fmaf(x, g_cosA[a], 63.5f));
            tt = fminf(fmaxf(tt, 0.0f), 127.0f);
            int   t0 = (int)tt;
            int   t1 = min(t0 + 1, 127);
            float w1 = tt - (float)t0;
            float w0 = 1.0f - w1;
            float wv = g_wv[a];
            int v0 = g_v0[a], v1 = g_v1[a];
            gp[v0 * 128 + t0] += w0 * (1.0f - wv);
            gp[v1 * 128 + t0] += w0 * wv;
            gp[v0 * 128 + t1] += w1 * (1.0f - wv);
            gp[v1 * 128 + t1] += w1 * wv;
        }
    }
    __syncthreads();

    for (int idx = tid; idx < 32768; idx += 128) {
        int pl = idx >> 10, kv = idx & 1023;
        int p = blockIdx.x * 32 + pl;
        int pt = p >> 7, r = p & 127;
        int kc = kv >> 6, c = kv & 63;
        uint32_t o = (uint32_t)(pt * 16 + kc) * 8192u + (swz(r * 128 + c * 2) >> 1);
        float val = g[idx];
        __nv_bfloat16 hi = __float2bfloat16(val);
        dGh[o] = hi;
        dGl[o] = __float2bfloat16(val - __bfloat162float(hi));
    }
}

// ---------------------------------------------------------------------------
static __device__ __forceinline__ uint32_t smem_u32(const void* p) {
    uint32_t a;
    asm("{ .reg .u64 t; cvta.to.shared.u64 t, %1; cvt.u32.u64 %0, t; }" : "=r"(a) : "l"(p));
    return a;
}
static __device__ __forceinline__ void cp16(uint32_t dst, const void* src) {
    asm volatile("cp.async.cg.shared.global [%0], [%1], 16;" :: "r"(dst), "l"(src));
}
#define LDSM4(r, addr) \
    asm volatile("ldmatrix.sync.aligned.m8n8.x4.shared.b16 {%0,%1,%2,%3}, [%4];" \
        : "=r"((r)[0]), "=r"((r)[1]), "=r"((r)[2]), "=r"((r)[3]) : "r"(addr))
#define MMA16816(c, a, b0, b1) \
    asm volatile("mma.sync.aligned.m16n8k16.row.col.f32.bf16.bf16.f32 " \
        "{%0,%1,%2,%3}, {%4,%5,%6,%7}, {%8,%9}, {%0,%1,%2,%3};" \
        : "+f"((c)[0]), "+f"((c)[1]), "+f"((c)[2]), "+f"((c)[3]) \
        : "r"((a)[0]), "r"((a)[1]), "r"((a)[2]), "r"((a)[3]), "r"(b0), "r"(b1))

__global__ void __launch_bounds__(256, 1) fbp_gemm(float* __restrict__ out) {
    extern __shared__ unsigned char smraw[];
    const uint32_t sb0 = smem_u32(smraw);
    const uint32_t sb  = (sb0 + 1023u) & ~1023u;
    float* Cp = (float*)(smraw + (sb - sb0));      // aligned generic pointer

    const int tid = threadIdx.x, wid = tid >> 5, lane = tid & 31;
    const int ptile = blockIdx.x;                  // 0..127
    const int stile = blockIdx.y;                  // 0..15

    const __nv_bfloat16* gAh = dGh + (size_t)ptile * 131072;
    const __nv_bfloat16* gAl = dGl + (size_t)ptile * 131072;
    const __nv_bfloat16* gBh = dFh + (size_t)stile * 131072;
    const __nv_bfloat16* gBl = dFl + (size_t)stile * 131072;

    const int mbase = (wid >> 2) * 64;             // 2 M blocks of 64
    const int nbase = (wid & 3) * 32;              // 4 N blocks of 32

    // per-lane ldmatrix row/koff decomposition; swizzle reduces to a const XOR
    const uint32_t xmask = (uint32_t)(lane & 7) << 4;
    const uint32_t arow  = (uint32_t)(lane & 15);
    const uint32_t akoff = (uint32_t)((lane >> 4) << 4);
    const uint32_t brow  = (uint32_t)((lane & 7) | ((lane & 16) >> 1));
    const uint32_t bkoff = (uint32_t)((lane & 8) << 1);

    float C[4][4][4];
    #pragma unroll
    for (int i = 0; i < 4; i++)
        #pragma unroll
        for (int j = 0; j < 4; j++)
            #pragma unroll
            for (int q = 0; q < 4; q++) C[i][j][q] = 0.0f;

    auto copy_chunk = [&](int c, int s) {
        uint32_t st = sb + (uint32_t)s * STAGE_B;
        const __nv_bfloat16* srcs[4] = { gAh + c * 8192, gAl + c * 8192,
                                         gBh + c * 8192, gBl + c * 8192 };
        #pragma unroll
        for (int b = 0; b < 4; b++)
            #pragma unroll
            for (int p = 0; p < 4; p++)
                cp16(st + (uint32_t)(b * 16384 + p * 4096 + tid * 16),
                     (const char*)srcs[b] + p * 4096 + tid * 16);
        asm volatile("cp.async.commit_group;" ::: "memory");
    };

    copy_chunk(0, 0);
    copy_chunk(1, 1);

    for (int c = 0; c < NCHUNK; c++) {
        if (c < NCHUNK - 1) asm volatile("cp.async.wait_group 1;" ::: "memory");
        else                asm volatile("cp.async.wait_group 0;" ::: "memory");
        __syncthreads();

        const uint32_t st = sb + (uint32_t)(c & 1) * STAGE_B;
        const uint32_t aH = st, aL = st + 16384, bH = st + 32768, bL = st + 49152;

        #pragma unroll
        for (int kk = 0; kk < 4; kk++) {
            const uint32_t kA = ((uint32_t)(kk * 32) + akoff) ^ xmask;
            const uint32_t kB = ((uint32_t)(kk * 32) + bkoff) ^ xmask;

            uint32_t ah[4][4], al[4][4], bh[4][2], bl[4][2];
            #pragma unroll
            for (int mt = 0; mt < 4; mt++) {
                uint32_t ro = (uint32_t)(mbase + mt * 16 + arow) * 128u;
                LDSM4(ah[mt], aH + ro + kA);
                LDSM4(al[mt], aL + ro + kA);
            }
            #pragma unroll
            for (int h = 0; h < 2; h++) {
                uint32_t ro = (uint32_t)(nbase + h * 16 + brow) * 128u;
                uint32_t rt[4];
                LDSM4(rt, bH + ro + kB);
                bh[2*h][0] = rt[0]; bh[2*h][1] = rt[1];
                bh[2*h+1][0] = rt[2]; bh[2*h+1][1] = rt[3];
                LDSM4(rt, bL + ro + kB);
                bl[2*h][0] = rt[0]; bl[2*h][1] = rt[1];
                bl[2*h+1][0] = rt[2]; bl[2*h+1][1] = rt[3];
            }
            #pragma unroll
            for (int mt = 0; mt < 4; mt++)
                #pragma unroll
                for (int nt = 0; nt < 4; nt++) {
                    MMA16816(C[mt][nt], ah[mt], bh[nt][0], bh[nt][1]);
                    MMA16816(C[mt][nt], ah[mt], bl[nt][0], bl[nt][1]);
                    MMA16816(C[mt][nt], al[mt], bh[nt][0], bh[nt][1]);
                }
        }
        __syncthreads();
        if (c + 2 < NCHUNK) copy_chunk(c + 2, c & 1);
    }

    // Epilogue: transpose C into SMEM as [slice n][pixel m], then coalesced out.
    __syncthreads();   // all mma reads done; smem free for reuse
    #pragma unroll
    for (int mt = 0; mt < 4; mt++)
        #pragma unroll
        for (int nt = 0; nt < 4; nt++) {
            int m0 = mbase + mt * 16 + (lane >> 2);
            int n0 = nbase + nt * 8 + 2 * (lane & 3);
            Cp[(n0    ) * 132 + m0    ] = C[mt][nt][0];
            Cp[(n0 + 1) * 132 + m0    ] = C[mt][nt][1];
            Cp[(n0    ) * 132 + m0 + 8] = C[mt][nt][2];
            Cp[(n0 + 1) * 132 + m0 + 8] = C[mt][nt][3];
        }
    __syncthreads();

    const int px = (tid & 31) * 4;
    #pragma unroll
    for (int i = 0; i < 16; i++) {
        int n = (tid >> 5) + i * 8;
        float4 v = *(const float4*)(Cp + n * 132 + px);
        *(float4*)(out + (size_t)(stile * 128 + n) * 16384 + ptile * 128 + px) = v;
    }
}

// ---------------------------------------------------------------------------
extern "C" void kernel_launch(void* const* d_in, const int* in_sizes, int n_in,
                              void* d_out, int out_size) {
    (void)in_sizes; (void)n_in; (void)out_size;
    cudaFuncSetAttribute(fbp_gmat, cudaFuncAttributeMaxDynamicSharedMemorySize, 131072);
    cudaFuncSetAttribute(fbp_gemm, cudaFuncAttributeMaxDynamicSharedMemorySize, GEMM_SMEM);

    fbp_setup<<<1, 128>>>();
    Ptrs P;
    for (int i = 0; i < 8; i++) P.p[i] = (const float*)d_in[i];
    fbp_filter<<<2048, 128>>>(P);
    fbp_gmat<<<512, 128, 131072>>>();
    fbp_gemm<<<dim3(128, 16), 256, GEMM_SMEM>>>((float*)d_out);
}